// round 3
// baseline (speedup 1.0000x reference)
#include <cuda_runtime.h>
#include <math.h>

#define TOK_TOTAL 32768
#define NTOK 1024
#define BATCH 32
#define C_DIM 4096
#define CH 2048
#define D_DIM 64

// ---- scratch (device globals; no allocation) ----
__device__ float g_mu[TOK_TOTAL];
__device__ float g_rstd[TOK_TOTAL];
__device__ float g_colsum[4 * BATCH * CH];   // [nsplit][b][c]
__device__ float g_C[BATCH * D_DIM];
__device__ float g_T[D_DIM];
__device__ float g_w1q[CH * D_DIM];          // paired layout: [(c/2)][d*2 + (c&1)]

// K0: precompute lnw-scaled, pair-interleaved lower w1
__global__ void k0_w1q(const float* __restrict__ lnw, const float* __restrict__ w1) {
    int idx = blockIdx.x * 256 + threadIdx.x;       // 0..131071
    int c = idx >> 6, d = idx & 63;
    float v = lnw[c] * w1[c * 64 + d];
    g_w1q[(c >> 1) * 128 + d * 2 + (c & 1)] = v;
}

// K0b: T[d] = sum_{c<2048} lnw[c]*w1[c,d]
__global__ void k0_T(const float* __restrict__ lnw, const float* __restrict__ w1) {
    __shared__ float red[256];
    int d = blockIdx.x, t = threadIdx.x;
    float acc = 0.f;
    for (int c = t; c < CH; c += 256) acc += lnw[c] * w1[c * 64 + d];
    red[t] = acc; __syncthreads();
    for (int s = 128; s > 0; s >>= 1) { if (t < s) red[t] += red[t + s]; __syncthreads(); }
    if (t == 0) g_T[d] = red[0];
}

// K1: per-token mean / rstd (warp per token)
__global__ void __launch_bounds__(256) k1_stats(const float4* __restrict__ x4) {
    int warp = threadIdx.x >> 5, lane = threadIdx.x & 31;
    int tok = blockIdx.x * 8 + warp;
    const float4* row = x4 + (size_t)tok * 1024;
    float s = 0.f, q = 0.f;
    #pragma unroll 8
    for (int i = 0; i < 32; i++) {
        float4 v = row[i * 32 + lane];
        s += v.x + v.y + v.z + v.w;
        q += v.x * v.x + v.y * v.y + v.z * v.z + v.w * v.w;
    }
    #pragma unroll
    for (int o = 16; o; o >>= 1) {
        s += __shfl_xor_sync(0xffffffffu, s, o);
        q += __shfl_xor_sync(0xffffffffu, q, o);
    }
    if (lane == 0) {
        float mu = s * (1.f / 4096.f);
        float var = q * (1.f / 4096.f) - mu * mu;
        g_mu[tok] = mu;
        g_rstd[tok] = rsqrtf(var + 1e-5f);
    }
}

// K2: partial column sums of rstd_n * x[b,n,2048+c] over n-chunks
__global__ void __launch_bounds__(256) k2_colsum(const float* __restrict__ x) {
    int c = blockIdx.x * 256 + threadIdx.x;         // 0..2047
    int b = blockIdx.y;
    int nb = blockIdx.z * 256;
    const float* base = x + ((size_t)(b * NTOK + nb)) * C_DIM + CH + c;
    const float* rs = g_rstd + b * NTOK + nb;
    float acc = 0.f;
    #pragma unroll 8
    for (int i = 0; i < 256; i++)
        acc = fmaf(rs[i], base[(size_t)i * C_DIM], acc);
    g_colsum[((blockIdx.z * BATCH) + b) * CH + c] = acc;
}

// K2b: per-batch constant C[b][d] = b1 + U_lower + sum_c' gx[b,c']*w1u[c',d]
__global__ void __launch_bounds__(512) k2b_C(const float* __restrict__ lnw,
                                             const float* __restrict__ lnb,
                                             const float* __restrict__ w1,
                                             const float* __restrict__ b1) {
    __shared__ float red[512];
    __shared__ float sR;
    int b = blockIdx.x, t = threadIdx.x;

    // R_b = sum_n rstd_n * mu_n
    float r = 0.f;
    for (int n = t; n < NTOK; n += 512)
        r += g_rstd[b * NTOK + n] * g_mu[b * NTOK + n];
    red[t] = r; __syncthreads();
    for (int s = 256; s > 0; s >>= 1) { if (t < s) red[t] += red[t + s]; __syncthreads(); }
    if (t == 0) sR = red[0];
    __syncthreads();
    float Rb = sR;

    int d = t & 63;
    int chunk = t >> 6;                 // 0..7, each covers 256 c's
    float acc = 0.f;
    for (int cc = 0; cc < 256; cc++) {
        int c = chunk * 256 + cc;
        float cs = g_colsum[(0 * BATCH + b) * CH + c] + g_colsum[(1 * BATCH + b) * CH + c]
                 + g_colsum[(2 * BATCH + b) * CH + c] + g_colsum[(3 * BATCH + b) * CH + c];
        float cm = (cs - Rb) * (1.f / 1024.f);
        float gx = lnw[CH + c] * cm + lnb[CH + c];
        acc = fmaf(gx, w1[(CH + c) * 64 + d], acc);
    }
    for (int cc = 0; cc < 256; cc++) {  // lower-half bias term U[d]
        int c = chunk * 256 + cc;
        acc = fmaf(lnb[c], w1[c * 64 + d], acc);
    }
    __syncthreads();
    red[t] = acc; __syncthreads();
    if (t < 64) {
        float sum = b1[d];
        #pragma unroll
        for (int k = 0; k < 8; k++) sum += red[d + 64 * k];
        g_C[b * 64 + d] = sum;
    }
}

// K3: per-token matvec S[d], gelu, logits, keep decision, gated output write.
// 64 tokens / CTA, 8 tokens / warp, d-pair / lane. FFMA-bound by design.
__global__ void __launch_bounds__(256, 4) k3_main(
    const float* __restrict__ x, const float* __restrict__ gumbel,
    const float* __restrict__ w2, const float* __restrict__ b2,
    float* __restrict__ out)
{
    __shared__ float sx[64 * 64];   // [tok][c] 16 KiB
    __shared__ float sw[64 * 64];   // w1q tile 16 KiB
    __shared__ float skeep[64];

    const int tid = threadIdx.x;
    const int wid = tid >> 5, lane = tid & 31;
    const int tokBase = blockIdx.x * 64;
    const int b = tokBase >> 10;

    const int d0 = lane * 2, d1 = lane * 2 + 1;
    const float T0 = g_T[d0], T1 = g_T[d1];
    const float C0 = g_C[b * 64 + d0], C1 = g_C[b * 64 + d1];
    const float w200 = w2[d0 * 2 + 0], w201 = w2[d0 * 2 + 1];
    const float w210 = w2[d1 * 2 + 0], w211 = w2[d1 * 2 + 1];

    float acc0[8], acc1[8];
    #pragma unroll
    for (int i = 0; i < 8; i++) { acc0[i] = 0.f; acc1[i] = 0.f; }

    for (int tile = 0; tile < 32; tile++) {
        int c0 = tile * 64;
        #pragma unroll
        for (int i = 0; i < 4; i++) {          // x tile: 1024 float4
            int j = tid + 256 * i;
            int tk = j >> 4, cf = j & 15;
            float4 v = *(const float4*)(x + ((size_t)(tokBase + tk)) * C_DIM + c0 + cf * 4);
            *(float4*)&sx[tk * 64 + cf * 4] = v;
        }
        const float4* wsrc = (const float4*)(g_w1q + (c0 >> 1) * 128);
        #pragma unroll
        for (int i = 0; i < 4; i++)            // w tile: contiguous 4096 floats
            ((float4*)sw)[tid + 256 * i] = wsrc[tid + 256 * i];
        __syncthreads();

        #pragma unroll
        for (int cg = 0; cg < 16; cg++) {
            int c = cg * 4;
            float4 wA = *(const float4*)&sw[(c >> 1) * 128 + lane * 4];       // c,c+1 x d0,d1
            float4 wB = *(const float4*)&sw[((c >> 1) + 1) * 128 + lane * 4]; // c+2,c+3 x d0,d1
            #pragma unroll
            for (int tt = 0; tt < 8; tt++) {
                float4 xv = *(const float4*)&sx[(wid * 8 + tt) * 64 + c];
                acc0[tt] = fmaf(xv.x, wA.x, acc0[tt]);
                acc0[tt] = fmaf(xv.y, wA.y, acc0[tt]);
                acc0[tt] = fmaf(xv.z, wB.x, acc0[tt]);
                acc0[tt] = fmaf(xv.w, wB.y, acc0[tt]);
                acc1[tt] = fmaf(xv.x, wA.z, acc1[tt]);
                acc1[tt] = fmaf(xv.y, wA.w, acc1[tt]);
                acc1[tt] = fmaf(xv.z, wB.z, acc1[tt]);
                acc1[tt] = fmaf(xv.w, wB.w, acc1[tt]);
            }
        }
        __syncthreads();
    }

    // epilogue: pre-act -> gelu -> logits -> keep
    #pragma unroll
    for (int tt = 0; tt < 8; tt++) {
        int tl = wid * 8 + tt;
        int gtok = tokBase + tl;
        float mu = g_mu[gtok], rstd = g_rstd[gtok];
        float m = mu * rstd;
        float pre0 = fmaf(rstd, acc0[tt], fmaf(-m, T0, C0));
        float pre1 = fmaf(rstd, acc1[tt], fmaf(-m, T1, C1));
        float h0 = 0.5f * pre0 * (1.f + erff(pre0 * 0.70710678118654752f));
        float h1 = 0.5f * pre1 * (1.f + erff(pre1 * 0.70710678118654752f));
        float p0 = h0 * w200 + h1 * w210;
        float p1 = h0 * w201 + h1 * w211;
        #pragma unroll
        for (int o = 16; o; o >>= 1) {
            p0 += __shfl_xor_sync(0xffffffffu, p0, o);
            p1 += __shfl_xor_sync(0xffffffffu, p1, o);
        }
        if (lane == 0) {
            float z0 = p0 + b2[0] + gumbel[gtok * 2 + 0];
            float z1 = p1 + b2[1] + gumbel[gtok * 2 + 1];
            skeep[tl] = (z0 >= z1) ? 1.f : 0.f;   // argmax ties -> index 0 -> keep
        }
    }
    __syncthreads();

    // gated output: skip the read entirely for dropped tokens
    const float4* x4 = (const float4*)x;
    float4* out4 = (float4*)out;
    for (int t = 0; t < 64; t++) {
        size_t rbase = ((size_t)(tokBase + t)) * 1024;
        if (skeep[t] != 0.f) {
            #pragma unroll 4
            for (int j = tid; j < 1024; j += 256) out4[rbase + j] = x4[rbase + j];
        } else {
            float4 z = make_float4(0.f, 0.f, 0.f, 0.f);
            #pragma unroll 4
            for (int j = tid; j < 1024; j += 256) out4[rbase + j] = z;
        }
    }
}

extern "C" void kernel_launch(void* const* d_in, const int* in_sizes, int n_in,
                              void* d_out, int out_size) {
    const float* x      = (const float*)d_in[0];   // (32,1024,4096)
    const float* gumbel = (const float*)d_in[1];   // (32,1024,2)
    const float* lnw    = (const float*)d_in[2];   // (4096)
    const float* lnb    = (const float*)d_in[3];   // (4096)
    const float* w1     = (const float*)d_in[4];   // (4096,64)
    const float* b1     = (const float*)d_in[5];   // (64)
    const float* w2     = (const float*)d_in[6];   // (64,2)
    const float* b2     = (const float*)d_in[7];   // (2)
    float* out = (float*)d_out;

    k0_w1q<<<512, 256>>>(lnw, w1);
    k0_T<<<64, 256>>>(lnw, w1);
    k1_stats<<<4096, 256>>>((const float4*)x);
    k2_colsum<<<dim3(8, 32, 4), 256>>>(x);
    k2b_C<<<32, 512>>>(lnw, lnb, w1, b1);
    k3_main<<<512, 256>>>(x, gumbel, w2, b2, out);
}

// round 11
// speedup vs baseline: 1.1448x; 1.1448x over previous
#include <cuda_runtime.h>
#include <math.h>

#define TOK_TOTAL 32768
#define NTOK 1024
#define BATCH 32
#define C_DIM 4096
#define CH 2048
#define D_DIM 64

typedef unsigned long long ull;

// packed fp32x2 FMA: a.lo += x.lo*w.lo; a.hi += x.hi*w.hi  (exact fp32 rn per lane)
#define FMA2(a, xv, wv) asm("fma.rn.f32x2 %0, %1, %2, %0;" : "+l"(a) : "l"(xv), "l"(wv))
#define PACK2(dst, f)   asm("mov.b64 %0, {%1, %1};" : "=l"(dst) : "r"(__float_as_uint(f)))
#define UNPACK2(lo, hi, src) asm("mov.b64 {%0, %1}, %2;" : "=r"(lo), "=r"(hi) : "l"(src))

// ---- scratch (device globals; no allocation) ----
__device__ float g_mu[TOK_TOTAL];
__device__ float g_rstd[TOK_TOTAL];
__device__ float g_colsum[16 * BATCH * CH];  // [b][slice][c] : (b*16+s)*2048+c
__device__ float g_C[BATCH * D_DIM];
__device__ float g_T[D_DIM];
__device__ float g_w1s[CH * D_DIM];          // lnw-scaled lower w1, row-major [c][d]

// K0: lnw-scaled lower w1, plain row-major
__global__ void k0_w1s(const float* __restrict__ lnw, const float* __restrict__ w1) {
    int idx = blockIdx.x * 256 + threadIdx.x;       // 0..131071
    g_w1s[idx] = lnw[idx >> 6] * w1[idx];
}

// K0b: T[d] = sum_{c<2048} lnw[c]*w1[c,d]
__global__ void k0_T(const float* __restrict__ lnw, const float* __restrict__ w1) {
    __shared__ float red[256];
    int d = blockIdx.x, t = threadIdx.x;
    float acc = 0.f;
    for (int c = t; c < CH; c += 256) acc += lnw[c] * w1[c * 64 + d];
    red[t] = acc; __syncthreads();
    for (int s = 128; s > 0; s >>= 1) { if (t < s) red[t] += red[t + s]; __syncthreads(); }
    if (t == 0) g_T[d] = red[0];
}

// K1f: fused per-token stats + upper-half weighted colsum, single pass over x.
// Block of 256 threads handles 64 tokens; upper-half values held in registers
// across the rstd reduction so x is read exactly once.
__global__ void __launch_bounds__(256) k1f(const float* __restrict__ x) {
    __shared__ float sred[8], qred[8];
    const int t = threadIdx.x;
    const int lane = t & 31, wid = t >> 5;
    const int tokBase = blockIdx.x * 64;
    const int b = blockIdx.x >> 4;
    const int slice = blockIdx.x & 15;

    float acc[8];
    #pragma unroll
    for (int i = 0; i < 8; i++) acc[i] = 0.f;

    for (int tok = 0; tok < 64; tok++) {
        const float4* row4 = (const float4*)(x + (size_t)(tokBase + tok) * C_DIM);
        float4 v0 = row4[t];
        float4 v1 = row4[t + 256];
        float4 v2 = row4[t + 512];   // c = 2048 + 4t .. +3
        float4 v3 = row4[t + 768];   // c = 3072 + 4t .. +3
        float s = v0.x + v0.y + v0.z + v0.w + v1.x + v1.y + v1.z + v1.w
                + v2.x + v2.y + v2.z + v2.w + v3.x + v3.y + v3.z + v3.w;
        float q = v0.x*v0.x + v0.y*v0.y + v0.z*v0.z + v0.w*v0.w
                + v1.x*v1.x + v1.y*v1.y + v1.z*v1.z + v1.w*v1.w
                + v2.x*v2.x + v2.y*v2.y + v2.z*v2.z + v2.w*v2.w
                + v3.x*v3.x + v3.y*v3.y + v3.z*v3.z + v3.w*v3.w;
        #pragma unroll
        for (int o = 16; o; o >>= 1) {
            s += __shfl_xor_sync(0xffffffffu, s, o);
            q += __shfl_xor_sync(0xffffffffu, q, o);
        }
        if (lane == 0) { sred[wid] = s; qred[wid] = q; }
        __syncthreads();
        float st = sred[0] + sred[1] + sred[2] + sred[3]
                 + sred[4] + sred[5] + sred[6] + sred[7];
        float qt = qred[0] + qred[1] + qred[2] + qred[3]
                 + qred[4] + qred[5] + qred[6] + qred[7];
        __syncthreads();   // smem reusable next token
        float mu = st * (1.f / 4096.f);
        float var = qt * (1.f / 4096.f) - mu * mu;
        float rstd = rsqrtf(var + 1e-5f);
        if (t == tok) { g_mu[tokBase + tok] = mu; g_rstd[tokBase + tok] = rstd; }
        acc[0] = fmaf(rstd, v2.x, acc[0]);
        acc[1] = fmaf(rstd, v2.y, acc[1]);
        acc[2] = fmaf(rstd, v2.z, acc[2]);
        acc[3] = fmaf(rstd, v2.w, acc[3]);
        acc[4] = fmaf(rstd, v3.x, acc[4]);
        acc[5] = fmaf(rstd, v3.y, acc[5]);
        acc[6] = fmaf(rstd, v3.z, acc[6]);
        acc[7] = fmaf(rstd, v3.w, acc[7]);
    }
    float* dst = g_colsum + (size_t)(b * 16 + slice) * CH;
    #pragma unroll
    for (int k = 0; k < 4; k++) dst[4 * t + k] = acc[k];          // c_upper-2048 = 4t+k
    #pragma unroll
    for (int k = 0; k < 4; k++) dst[1024 + 4 * t + k] = acc[4 + k];
}

// K2b: per-batch constant C[b][d]
__global__ void __launch_bounds__(512) k2b_C(const float* __restrict__ lnw,
                                             const float* __restrict__ lnb,
                                             const float* __restrict__ w1,
                                             const float* __restrict__ b1) {
    __shared__ float scol[2048];
    __shared__ float red[512];
    __shared__ float sR;
    int b = blockIdx.x, t = threadIdx.x;

    // reduce 16 colsum slices -> scol
    float4 a = make_float4(0.f, 0.f, 0.f, 0.f);
    #pragma unroll
    for (int s = 0; s < 16; s++) {
        float4 v = *(const float4*)(g_colsum + (size_t)(b * 16 + s) * CH + 4 * t);
        a.x += v.x; a.y += v.y; a.z += v.z; a.w += v.w;
    }
    *(float4*)&scol[4 * t] = a;

    // R_b = sum_n rstd_n * mu_n
    float r = 0.f;
    for (int n = t; n < NTOK; n += 512)
        r += g_rstd[b * NTOK + n] * g_mu[b * NTOK + n];
    red[t] = r; __syncthreads();
    for (int s = 256; s > 0; s >>= 1) { if (t < s) red[t] += red[t + s]; __syncthreads(); }
    if (t == 0) sR = red[0];
    __syncthreads();
    float Rb = sR;

    int d = t & 63;
    int chunk = t >> 6;                 // 0..7, each covers 256 c's
    float acc = 0.f;
    for (int cc = 0; cc < 256; cc++) {
        int c = chunk * 256 + cc;
        float cm = (scol[c] - Rb) * (1.f / 1024.f);
        float gx = lnw[CH + c] * cm + lnb[CH + c];
        acc = fmaf(gx, w1[(CH + c) * 64 + d], acc);
    }
    for (int cc = 0; cc < 256; cc++) {  // lower-half bias term U[d]
        int c = chunk * 256 + cc;
        acc = fmaf(lnb[c], w1[c * 64 + d], acc);
    }
    __syncthreads();
    red[t] = acc; __syncthreads();
    if (t < 64) {
        float sum = b1[d];
        #pragma unroll
        for (int k = 0; k < 8; k++) sum += red[d + 64 * k];
        g_C[b * 64 + d] = sum;
    }
}

// K3: matvec (lower half only) with packed fp32x2 FMA over token pairs,
// gelu -> logits -> keep -> gated copy. 64 tokens/CTA, 8 tokens/warp, d-pair/lane.
#define SXT_STRIDE 66
__global__ void __launch_bounds__(256, 4) k3_main(
    const float* __restrict__ x, const float* __restrict__ gumbel,
    const float* __restrict__ w2, const float* __restrict__ b2,
    float* __restrict__ out)
{
    __shared__ float sxt[64 * SXT_STRIDE];   // [c][tok], padded
    __shared__ float sw[64 * 64];            // [c][d]
    __shared__ float skeep[64];

    const int tid = threadIdx.x;
    const int wid = tid >> 5, lane = tid & 31;
    const int tokBase = blockIdx.x * 64;
    const int b = tokBase >> 10;

    const int d0 = lane * 2, d1 = lane * 2 + 1;
    const float T0 = g_T[d0], T1 = g_T[d1];
    const float C0 = g_C[b * 64 + d0], C1 = g_C[b * 64 + d1];
    const float w200 = w2[d0 * 2 + 0], w201 = w2[d0 * 2 + 1];
    const float w210 = w2[d1 * 2 + 0], w211 = w2[d1 * 2 + 1];

    ull a0[4], a1[4];   // [token-pair]: packed (tok even, tok odd) accumulators for d0/d1
    #pragma unroll
    for (int i = 0; i < 4; i++) { a0[i] = 0ull; a1[i] = 0ull; }

    for (int tile = 0; tile < 32; tile++) {
        int c0 = tile * 64;
        #pragma unroll
        for (int i = 0; i < 4; i++) {          // coalesced read, transposed store
            int j = tid + 256 * i;
            int tk = j >> 4, cf = j & 15;
            float4 v = *(const float4*)(x + (size_t)(tokBase + tk) * C_DIM + c0 + cf * 4);
            int cb = 4 * cf;
            sxt[(cb + 0) * SXT_STRIDE + tk] = v.x;
            sxt[(cb + 1) * SXT_STRIDE + tk] = v.y;
            sxt[(cb + 2) * SXT_STRIDE + tk] = v.z;
            sxt[(cb + 3) * SXT_STRIDE + tk] = v.w;
        }
        const float4* wsrc = (const float4*)(g_w1s + c0 * 64);
        #pragma unroll
        for (int i = 0; i < 4; i++)
            ((float4*)sw)[tid + 256 * i] = wsrc[tid + 256 * i];
        __syncthreads();

        #pragma unroll 8
        for (int c = 0; c < 64; c++) {
            float2 wv = *(const float2*)&sw[c * 64 + lane * 2];
            ull w0, w1p;
            PACK2(w0, wv.x);
            PACK2(w1p, wv.y);
            const float* xr = &sxt[c * SXT_STRIDE + wid * 8];
            ull x01 = *(const ull*)&xr[0];
            ull x23 = *(const ull*)&xr[2];
            ull x45 = *(const ull*)&xr[4];
            ull x67 = *(const ull*)&xr[6];
            FMA2(a0[0], x01, w0);  FMA2(a1[0], x01, w1p);
            FMA2(a0[1], x23, w0);  FMA2(a1[1], x23, w1p);
            FMA2(a0[2], x45, w0);  FMA2(a1[2], x45, w1p);
            FMA2(a0[3], x67, w0);  FMA2(a1[3], x67, w1p);
        }
        __syncthreads();
    }

    // epilogue: unpack, pre-act -> gelu -> logits -> keep
    #pragma unroll
    for (int p = 0; p < 4; p++) {
        unsigned int u0lo, u0hi, u1lo, u1hi;
        UNPACK2(u0lo, u0hi, a0[p]);
        UNPACK2(u1lo, u1hi, a1[p]);
        #pragma unroll
        for (int e = 0; e < 2; e++) {
            float s0 = __uint_as_float(e ? u0hi : u0lo);
            float s1 = __uint_as_float(e ? u1hi : u1lo);
            int tl = wid * 8 + 2 * p + e;
            int gtok = tokBase + tl;
            float mu = g_mu[gtok], rstd = g_rstd[gtok];
            float m = mu * rstd;
            float pre0 = fmaf(rstd, s0, fmaf(-m, T0, C0));
            float pre1 = fmaf(rstd, s1, fmaf(-m, T1, C1));
            float h0 = 0.5f * pre0 * (1.f + erff(pre0 * 0.70710678118654752f));
            float h1 = 0.5f * pre1 * (1.f + erff(pre1 * 0.70710678118654752f));
            float p0 = h0 * w200 + h1 * w210;
            float p1 = h0 * w201 + h1 * w211;
            #pragma unroll
            for (int o = 16; o; o >>= 1) {
                p0 += __shfl_xor_sync(0xffffffffu, p0, o);
                p1 += __shfl_xor_sync(0xffffffffu, p1, o);
            }
            if (lane == 0) {
                float z0 = p0 + b2[0] + gumbel[gtok * 2 + 0];
                float z1 = p1 + b2[1] + gumbel[gtok * 2 + 1];
                skeep[tl] = (z0 >= z1) ? 1.f : 0.f;
            }
        }
    }
    __syncthreads();

    // gated output: copy kept tokens, zero dropped
    const float4* x4 = (const float4*)x;
    float4* out4 = (float4*)out;
    for (int t = 0; t < 64; t++) {
        size_t rbase = ((size_t)(tokBase + t)) * 1024;
        if (skeep[t] != 0.f) {
            #pragma unroll 4
            for (int j = tid; j < 1024; j += 256) out4[rbase + j] = x4[rbase + j];
        } else {
            float4 z = make_float4(0.f, 0.f, 0.f, 0.f);
            #pragma unroll 4
            for (int j = tid; j < 1024; j += 256) out4[rbase + j] = z;
        }
    }
}

extern "C" void kernel_launch(void* const* d_in, const int* in_sizes, int n_in,
                              void* d_out, int out_size) {
    const float* x      = (const float*)d_in[0];   // (32,1024,4096)
    const float* gumbel = (const float*)d_in[1];   // (32,1024,2)
    const float* lnw    = (const float*)d_in[2];   // (4096)
    const float* lnb    = (const float*)d_in[3];   // (4096)
    const float* w1     = (const float*)d_in[4];   // (4096,64)
    const float* b1     = (const float*)d_in[5];   // (64)
    const float* w2     = (const float*)d_in[6];   // (64,2)
    const float* b2     = (const float*)d_in[7];   // (2)
    float* out = (float*)d_out;

    k0_w1s<<<512, 256>>>(lnw, w1);
    k0_T<<<64, 256>>>(lnw, w1);
    k1f<<<512, 256>>>(x);
    k2b_C<<<32, 512>>>(lnw, lnb, w1, b1);
    k3_main<<<512, 256>>>(x, gumbel, w2, b2, out);
}

// round 12
// speedup vs baseline: 1.2909x; 1.1277x over previous
#include <cuda_runtime.h>
#include <math.h>

#define TOK_TOTAL 32768
#define NTOK 1024
#define BATCH 32
#define C_DIM 4096
#define CH 2048
#define D_DIM 64

typedef unsigned long long ull;

// packed fp32x2 FMA: a.lo += x.lo*w.lo; a.hi += x.hi*w.hi  (exact fp32 rn per lane)
#define FMA2(a, xv, wv) asm("fma.rn.f32x2 %0, %1, %2, %0;" : "+l"(a) : "l"(xv), "l"(wv))
#define PACK2(dst, f)   asm("mov.b64 %0, {%1, %1};" : "=l"(dst) : "r"(__float_as_uint(f)))
#define UNPACK2(lo, hi, src) asm("mov.b64 {%0, %1}, %2;" : "=r"(lo), "=r"(hi) : "l"(src))

// ---- scratch (device globals; no allocation) ----
__device__ float g_mu[TOK_TOTAL];
__device__ float g_rstd[TOK_TOTAL];
__device__ float g_colsum[16 * BATCH * CH];  // [b][slice][c]
__device__ float g_Cpart[BATCH * 8 * D_DIM]; // [b][j][d] partial C
__device__ float g_T[D_DIM];
__device__ float g_U[D_DIM];                 // b1 + sum_lower lnb*w1
__device__ float g_w1s[CH * D_DIM];          // lnw-scaled lower w1, row-major [c][d]

// K0: merged prep. Blocks 0..511: scaled lower w1. Blocks 512..575: T[d], U[d].
__global__ void k0_prep(const float* __restrict__ lnw, const float* __restrict__ lnb,
                        const float* __restrict__ w1, const float* __restrict__ b1) {
    int bx = blockIdx.x, t = threadIdx.x;
    if (bx < 512) {
        int idx = bx * 256 + t;                 // 0..131071
        g_w1s[idx] = lnw[idx >> 6] * w1[idx];
        return;
    }
    __shared__ float redT[256], redU[256];
    int d = bx - 512;                           // 0..63
    float aT = 0.f, aU = 0.f;
    for (int c = t; c < CH; c += 256) {
        float w = w1[c * 64 + d];
        aT = fmaf(lnw[c], w, aT);
        aU = fmaf(lnb[c], w, aU);
    }
    redT[t] = aT; redU[t] = aU; __syncthreads();
    for (int s = 128; s > 0; s >>= 1) {
        if (t < s) { redT[t] += redT[t + s]; redU[t] += redU[t + s]; }
        __syncthreads();
    }
    if (t == 0) { g_T[d] = redT[0]; g_U[d] = redU[0] + b1[d]; }
}

// K1f: fused per-token stats + upper-half weighted colsum, single pass over x.
__global__ void __launch_bounds__(256) k1f(const float* __restrict__ x) {
    __shared__ float sred[8], qred[8];
    const int t = threadIdx.x;
    const int lane = t & 31, wid = t >> 5;
    const int tokBase = blockIdx.x * 64;
    const int b = blockIdx.x >> 4;
    const int slice = blockIdx.x & 15;

    float acc[8];
    #pragma unroll
    for (int i = 0; i < 8; i++) acc[i] = 0.f;

    for (int tok = 0; tok < 64; tok++) {
        const float4* row4 = (const float4*)(x + (size_t)(tokBase + tok) * C_DIM);
        float4 v0 = row4[t];
        float4 v1 = row4[t + 256];
        float4 v2 = row4[t + 512];
        float4 v3 = row4[t + 768];
        float s = v0.x + v0.y + v0.z + v0.w + v1.x + v1.y + v1.z + v1.w
                + v2.x + v2.y + v2.z + v2.w + v3.x + v3.y + v3.z + v3.w;
        float q = v0.x*v0.x + v0.y*v0.y + v0.z*v0.z + v0.w*v0.w
                + v1.x*v1.x + v1.y*v1.y + v1.z*v1.z + v1.w*v1.w
                + v2.x*v2.x + v2.y*v2.y + v2.z*v2.z + v2.w*v2.w
                + v3.x*v3.x + v3.y*v3.y + v3.z*v3.z + v3.w*v3.w;
        #pragma unroll
        for (int o = 16; o; o >>= 1) {
            s += __shfl_xor_sync(0xffffffffu, s, o);
            q += __shfl_xor_sync(0xffffffffu, q, o);
        }
        if (lane == 0) { sred[wid] = s; qred[wid] = q; }
        __syncthreads();
        float st = sred[0] + sred[1] + sred[2] + sred[3]
                 + sred[4] + sred[5] + sred[6] + sred[7];
        float qt = qred[0] + qred[1] + qred[2] + qred[3]
                 + qred[4] + qred[5] + qred[6] + qred[7];
        __syncthreads();
        float mu = st * (1.f / 4096.f);
        float var = qt * (1.f / 4096.f) - mu * mu;
        float rstd = rsqrtf(var + 1e-5f);
        if (t == tok) { g_mu[tokBase + tok] = mu; g_rstd[tokBase + tok] = rstd; }
        acc[0] = fmaf(rstd, v2.x, acc[0]);
        acc[1] = fmaf(rstd, v2.y, acc[1]);
        acc[2] = fmaf(rstd, v2.z, acc[2]);
        acc[3] = fmaf(rstd, v2.w, acc[3]);
        acc[4] = fmaf(rstd, v3.x, acc[4]);
        acc[5] = fmaf(rstd, v3.y, acc[5]);
        acc[6] = fmaf(rstd, v3.z, acc[6]);
        acc[7] = fmaf(rstd, v3.w, acc[7]);
    }
    float* dst = g_colsum + (size_t)(b * 16 + slice) * CH;
    #pragma unroll
    for (int k = 0; k < 4; k++) dst[4 * t + k] = acc[k];
    #pragma unroll
    for (int k = 0; k < 4; k++) dst[1024 + 4 * t + k] = acc[4 + k];
}

// K2b: parallel partial C. grid (32 b, 8 j), block 512.
// Each block: Rb reduce, gx for its 256-c window (smem), 32-MAC matvec, partial out.
__global__ void __launch_bounds__(512) k2b_part(const float* __restrict__ lnw,
                                                const float* __restrict__ lnb,
                                                const float* __restrict__ w1) {
    __shared__ float sgx[256];
    __shared__ float red[512];
    __shared__ float sRb;
    int b = blockIdx.x, j = blockIdx.y, t = threadIdx.x;

    const float* mu = g_mu + b * NTOK;
    const float* rs = g_rstd + b * NTOK;
    float r = rs[t] * mu[t] + rs[t + 512] * mu[t + 512];
    red[t] = r; __syncthreads();
    for (int s = 256; s > 0; s >>= 1) { if (t < s) red[t] += red[t + s]; __syncthreads(); }
    if (t == 0) sRb = red[0];
    __syncthreads();
    float Rb = sRb;

    if (t < 256) {
        int c = j * 256 + t;
        float cs = 0.f;
        #pragma unroll
        for (int s = 0; s < 16; s++) cs += g_colsum[(size_t)(b * 16 + s) * CH + c];
        float cm = (cs - Rb) * (1.f / 1024.f);
        sgx[t] = lnw[CH + c] * cm + lnb[CH + c];
    }
    __syncthreads();

    int d = t & 63, s = t >> 6;                  // 8 subs x 32 c each
    float acc = 0.f;
    const float* wrow = w1 + (size_t)(CH + j * 256 + s * 32) * 64 + d;
    #pragma unroll
    for (int cc = 0; cc < 32; cc++)
        acc = fmaf(sgx[s * 32 + cc], wrow[(size_t)cc * 64], acc);
    __syncthreads();
    red[t] = acc; __syncthreads();
    if (t < 64) {
        float sum = 0.f;
        #pragma unroll
        for (int k = 0; k < 8; k++) sum += red[k * 64 + t];
        g_Cpart[(b * 8 + j) * 64 + t] = sum;
    }
}

// K3: matvec with packed fp32x2 FMA over token pairs; gelu->logits->keep->gated copy.
#define SXT_STRIDE 66
__global__ void __launch_bounds__(256, 4) k3_main(
    const float* __restrict__ x, const float* __restrict__ gumbel,
    const float* __restrict__ w2, const float* __restrict__ b2,
    float* __restrict__ out)
{
    __shared__ float sxt[64 * SXT_STRIDE];
    __shared__ float sw[64 * 64];
    __shared__ float skeep[64];

    const int tid = threadIdx.x;
    const int wid = tid >> 5, lane = tid & 31;
    const int tokBase = blockIdx.x * 64;
    const int b = tokBase >> 10;

    const int d0 = lane * 2, d1 = lane * 2 + 1;
    const float T0 = g_T[d0], T1 = g_T[d1];
    float C0 = g_U[d0], C1 = g_U[d1];
    #pragma unroll
    for (int j = 0; j < 8; j++) {
        C0 += g_Cpart[(b * 8 + j) * 64 + d0];
        C1 += g_Cpart[(b * 8 + j) * 64 + d1];
    }
    const float w200 = w2[d0 * 2 + 0], w201 = w2[d0 * 2 + 1];
    const float w210 = w2[d1 * 2 + 0], w211 = w2[d1 * 2 + 1];

    ull a0[4], a1[4];
    #pragma unroll
    for (int i = 0; i < 4; i++) { a0[i] = 0ull; a1[i] = 0ull; }

    for (int tile = 0; tile < 32; tile++) {
        int c0 = tile * 64;
        #pragma unroll
        for (int i = 0; i < 4; i++) {
            int j = tid + 256 * i;
            int tk = j >> 4, cf = j & 15;
            float4 v = *(const float4*)(x + (size_t)(tokBase + tk) * C_DIM + c0 + cf * 4);
            int cb = 4 * cf;
            sxt[(cb + 0) * SXT_STRIDE + tk] = v.x;
            sxt[(cb + 1) * SXT_STRIDE + tk] = v.y;
            sxt[(cb + 2) * SXT_STRIDE + tk] = v.z;
            sxt[(cb + 3) * SXT_STRIDE + tk] = v.w;
        }
        const float4* wsrc = (const float4*)(g_w1s + c0 * 64);
        #pragma unroll
        for (int i = 0; i < 4; i++)
            ((float4*)sw)[tid + 256 * i] = wsrc[tid + 256 * i];
        __syncthreads();

        #pragma unroll 8
        for (int c = 0; c < 64; c++) {
            float2 wv = *(const float2*)&sw[c * 64 + lane * 2];
            ull w0, w1p;
            PACK2(w0, wv.x);
            PACK2(w1p, wv.y);
            const float* xr = &sxt[c * SXT_STRIDE + wid * 8];
            ull x01 = *(const ull*)&xr[0];
            ull x23 = *(const ull*)&xr[2];
            ull x45 = *(const ull*)&xr[4];
            ull x67 = *(const ull*)&xr[6];
            FMA2(a0[0], x01, w0);  FMA2(a1[0], x01, w1p);
            FMA2(a0[1], x23, w0);  FMA2(a1[1], x23, w1p);
            FMA2(a0[2], x45, w0);  FMA2(a1[2], x45, w1p);
            FMA2(a0[3], x67, w0);  FMA2(a1[3], x67, w1p);
        }
        __syncthreads();
    }

    #pragma unroll
    for (int p = 0; p < 4; p++) {
        unsigned int u0lo, u0hi, u1lo, u1hi;
        UNPACK2(u0lo, u0hi, a0[p]);
        UNPACK2(u1lo, u1hi, a1[p]);
        #pragma unroll
        for (int e = 0; e < 2; e++) {
            float s0 = __uint_as_float(e ? u0hi : u0lo);
            float s1 = __uint_as_float(e ? u1hi : u1lo);
            int tl = wid * 8 + 2 * p + e;
            int gtok = tokBase + tl;
            float mu = g_mu[gtok], rstd = g_rstd[gtok];
            float m = mu * rstd;
            float pre0 = fmaf(rstd, s0, fmaf(-m, T0, C0));
            float pre1 = fmaf(rstd, s1, fmaf(-m, T1, C1));
            float h0 = 0.5f * pre0 * (1.f + erff(pre0 * 0.70710678118654752f));
            float h1 = 0.5f * pre1 * (1.f + erff(pre1 * 0.70710678118654752f));
            float p0 = h0 * w200 + h1 * w210;
            float p1 = h0 * w201 + h1 * w211;
            #pragma unroll
            for (int o = 16; o; o >>= 1) {
                p0 += __shfl_xor_sync(0xffffffffu, p0, o);
                p1 += __shfl_xor_sync(0xffffffffu, p1, o);
            }
            if (lane == 0) {
                float z0 = p0 + b2[0] + gumbel[gtok * 2 + 0];
                float z1 = p1 + b2[1] + gumbel[gtok * 2 + 1];
                skeep[tl] = (z0 >= z1) ? 1.f : 0.f;
            }
        }
    }
    __syncthreads();

    const float4* x4 = (const float4*)x;
    float4* out4 = (float4*)out;
    for (int t = 0; t < 64; t++) {
        size_t rbase = ((size_t)(tokBase + t)) * 1024;
        if (skeep[t] != 0.f) {
            #pragma unroll 4
            for (int j = tid; j < 1024; j += 256) out4[rbase + j] = x4[rbase + j];
        } else {
            float4 z = make_float4(0.f, 0.f, 0.f, 0.f);
            #pragma unroll 4
            for (int j = tid; j < 1024; j += 256) out4[rbase + j] = z;
        }
    }
}

extern "C" void kernel_launch(void* const* d_in, const int* in_sizes, int n_in,
                              void* d_out, int out_size) {
    const float* x      = (const float*)d_in[0];   // (32,1024,4096)
    const float* gumbel = (const float*)d_in[1];   // (32,1024,2)
    const float* lnw    = (const float*)d_in[2];   // (4096)
    const float* lnb    = (const float*)d_in[3];   // (4096)
    const float* w1     = (const float*)d_in[4];   // (4096,64)
    const float* b1     = (const float*)d_in[5];   // (64)
    const float* w2     = (const float*)d_in[6];   // (64,2)
    const float* b2     = (const float*)d_in[7];   // (2)
    float* out = (float*)d_out;

    k0_prep<<<576, 256>>>(lnw, lnb, w1, b1);
    k1f<<<512, 256>>>(x);
    k2b_part<<<dim3(32, 8), 512>>>(lnw, lnb, w1);
    k3_main<<<512, 256>>>(x, gumbel, w2, b2, out);
}